// round 4
// baseline (speedup 1.0000x reference)
#include <cuda_runtime.h>
#include <math.h>

#define NN    10000
#define EIN   160000
#define ETOT  170000
#define NHEAD 8
#define HID   256
#define EPSI  1e-5f
#define SLOPE 0.2f

typedef unsigned long long ull;

// ---------------- scratch (device globals; no allocation allowed) ----------------
__device__ float d_h0[NN * HID];            // x @ W0 (layer0 features)
__device__ float d_hin[NN * HID];           // elu(bn(layer0))
__device__ float d_agg[NN * HID * NHEAD];   // per-head aggregated hin  [N,H,256]
__device__ float d_part[4 * NN * HID];      // split-K partials
__device__ float d_out0[NN * HID];
__device__ float d_out1[NN * HID];
__device__ float d_h2[NN * HID];
__device__ float d_ss[NN * NHEAD];
__device__ float d_sd[NN * NHEAD];
__device__ float d_wsrc[NHEAD * HID];       // folded a_src1 through W1
__device__ float d_wdst[NHEAD * HID];
__device__ float d_wcat[NHEAD * HID * HID]; // [ (h,k) , c ] permuted W1
__device__ int   d_counts[NN + 1];
__device__ int   d_offsets[NN + 1];
__device__ int   d_cursor[NN];
__device__ int   d_srcs[ETOT];
__device__ float d_alpha[ETOT * NHEAD];
__device__ float d_bnsum[HID];
__device__ float d_bnsum2[HID];
__device__ float d_mu[HID];
__device__ float d_rinv[HID];

// ---------------- CSR build ----------------
__global__ void count_kernel(const int* __restrict__ dst) {
    int i = blockIdx.x * blockDim.x + threadIdx.x;
    if (i >= ETOT) return;
    int d = (i < EIN) ? dst[i] : (i - EIN);
    atomicAdd(&d_counts[d], 1);
}

__global__ void scan_kernel() {
    __shared__ int sums[1024];
    const int n = NN;
    const int chunk = (n + 1023) / 1024;
    int tid = threadIdx.x;
    int start = tid * chunk;
    int local = 0;
    for (int i = 0; i < chunk; i++)
        if (start + i < n) local += d_counts[start + i];
    sums[tid] = local;
    __syncthreads();
    for (int off = 1; off < 1024; off <<= 1) {
        int v = (tid >= off) ? sums[tid - off] : 0;
        __syncthreads();
        sums[tid] += v;
        __syncthreads();
    }
    int run = (tid == 0) ? 0 : sums[tid - 1];
    for (int i = 0; i < chunk; i++) {
        if (start + i < n) {
            d_offsets[start + i] = run;
            run += d_counts[start + i];
        }
    }
    if (tid == 1023) d_offsets[n] = sums[1023];
}

__global__ void place_kernel(const int* __restrict__ src, const int* __restrict__ dst) {
    int i = blockIdx.x * blockDim.x + threadIdx.x;
    if (i >= ETOT) return;
    int s, d;
    if (i < EIN) { s = src[i]; d = dst[i]; }
    else         { s = d = i - EIN; }
    int pos = d_offsets[d] + atomicAdd(&d_cursor[d], 1);
    d_srcs[pos] = s;
}

// ---------------- attention scores (layer0: per-head feature dot) ----------------
__global__ void attn_scores(const float* __restrict__ h,
                            const float* __restrict__ a_src,
                            const float* __restrict__ a_dst, int C) {
    int w = (blockIdx.x * blockDim.x + threadIdx.x) >> 5;
    if (w >= NN * NHEAD) return;
    int node = w / NHEAD, head = w % NHEAD;
    int lane = threadIdx.x & 31;
    const float* hp = h + (size_t)node * NHEAD * C + head * C;
    const float* asrc = a_src + head * C;
    const float* adst = a_dst + head * C;
    float ss = 0.f, sd = 0.f;
    for (int c = lane; c < C; c += 32) {
        float hv = hp[c];
        ss += hv * asrc[c];
        sd += hv * adst[c];
    }
    #pragma unroll
    for (int o = 16; o > 0; o >>= 1) {
        ss += __shfl_xor_sync(0xffffffffu, ss, o);
        sd += __shfl_xor_sync(0xffffffffu, sd, o);
    }
    if (lane == 0) {
        d_ss[node * NHEAD + head] = ss;
        d_sd[node * NHEAD + head] = sd;
    }
}

// ---------------- layer1 scores: s[n,h] = dot(hin[n,:], wtilde[h,:]) ----------------
__global__ void attn_scores_lin(const float* __restrict__ hin) {
    int w = (blockIdx.x * blockDim.x + threadIdx.x) >> 5;
    if (w >= NN) return;
    int lane = threadIdx.x & 31;
    const float* hp = hin + (size_t)w * HID;
    float as[NHEAD], ad[NHEAD];
    #pragma unroll
    for (int h = 0; h < NHEAD; h++) { as[h] = 0.f; ad[h] = 0.f; }
    for (int c = lane; c < HID; c += 32) {
        float v = hp[c];
        #pragma unroll
        for (int h = 0; h < NHEAD; h++) {
            as[h] = fmaf(v, d_wsrc[h * HID + c], as[h]);
            ad[h] = fmaf(v, d_wdst[h * HID + c], ad[h]);
        }
    }
    #pragma unroll
    for (int h = 0; h < NHEAD; h++) {
        #pragma unroll
        for (int o = 16; o > 0; o >>= 1) {
            as[h] += __shfl_xor_sync(0xffffffffu, as[h], o);
            ad[h] += __shfl_xor_sync(0xffffffffu, ad[h], o);
        }
    }
    if (lane == 0) {
        #pragma unroll
        for (int h = 0; h < NHEAD; h++) {
            d_ss[w * NHEAD + h] = as[h];
            d_sd[w * NHEAD + h] = ad[h];
        }
    }
}

// ---------------- per-dst edge softmax ----------------
__global__ void edge_softmax() {
    int w = (blockIdx.x * blockDim.x + threadIdx.x) >> 5;
    if (w >= NN) return;
    int lane = threadIdx.x & 31;
    int beg = d_offsets[w], end = d_offsets[w + 1];
    float sd[NHEAD];
    #pragma unroll
    for (int h = 0; h < NHEAD; h++) sd[h] = d_sd[w * NHEAD + h];

    float mx[NHEAD];
    #pragma unroll
    for (int h = 0; h < NHEAD; h++) mx[h] = -1e30f;
    for (int p = beg + lane; p < end; p += 32) {
        int s = d_srcs[p];
        #pragma unroll
        for (int h = 0; h < NHEAD; h++) {
            float sc = d_ss[s * NHEAD + h] + sd[h];
            sc = (sc >= 0.f) ? sc : SLOPE * sc;
            mx[h] = fmaxf(mx[h], sc);
        }
    }
    #pragma unroll
    for (int h = 0; h < NHEAD; h++)
        #pragma unroll
        for (int o = 16; o > 0; o >>= 1)
            mx[h] = fmaxf(mx[h], __shfl_xor_sync(0xffffffffu, mx[h], o));

    float sum[NHEAD];
    #pragma unroll
    for (int h = 0; h < NHEAD; h++) sum[h] = 0.f;
    for (int p = beg + lane; p < end; p += 32) {
        int s = d_srcs[p];
        #pragma unroll
        for (int h = 0; h < NHEAD; h++) {
            float sc = d_ss[s * NHEAD + h] + sd[h];
            sc = (sc >= 0.f) ? sc : SLOPE * sc;
            sum[h] += __expf(sc - mx[h]);
        }
    }
    #pragma unroll
    for (int h = 0; h < NHEAD; h++)
        #pragma unroll
        for (int o = 16; o > 0; o >>= 1)
            sum[h] += __shfl_xor_sync(0xffffffffu, sum[h], o);

    float rinv[NHEAD];
    #pragma unroll
    for (int h = 0; h < NHEAD; h++) rinv[h] = 1.f / sum[h];

    for (int p = beg + lane; p < end; p += 32) {
        int s = d_srcs[p];
        #pragma unroll
        for (int h = 0; h < NHEAD; h++) {
            float sc = d_ss[s * NHEAD + h] + sd[h];
            sc = (sc >= 0.f) ? sc : SLOPE * sc;
            d_alpha[p * NHEAD + h] = __expf(sc - mx[h]) * rinv[h];
        }
    }
}

// ---------------- aggregation ----------------
// layer0: C=32 concat; thread t = channel, head = t>>5
__global__ void aggregate_c32(const float* __restrict__ h,
                              const float* __restrict__ bias,
                              float* __restrict__ out) {
    int nod = blockIdx.x;
    int t = threadIdx.x;
    int head = t >> 5;
    int beg = d_offsets[nod], end = d_offsets[nod + 1];
    float acc = 0.f;
    for (int p = beg; p < end; p++) {
        float a = d_alpha[p * NHEAD + head];
        acc = fmaf(h[(size_t)d_srcs[p] * HID + t], a, acc);
    }
    out[(size_t)nod * HID + t] = acc + bias[t];
}

// layer1 pre-GEMM aggregation: agg[n,h,k] = sum_p alpha[p,h] * hin[src_p, k]
__global__ void aggregate8(const float* __restrict__ hin, float* __restrict__ agg) {
    int nod = blockIdx.x;
    int t = threadIdx.x;
    int beg = d_offsets[nod], end = d_offsets[nod + 1];
    float acc[NHEAD];
    #pragma unroll
    for (int i = 0; i < NHEAD; i++) acc[i] = 0.f;
    for (int p = beg; p < end; p++) {
        int s = d_srcs[p];
        float v = hin[(size_t)s * HID + t];
        float al[NHEAD];
        #pragma unroll
        for (int i = 0; i < NHEAD; i++) al[i] = d_alpha[p * NHEAD + i];
        #pragma unroll
        for (int i = 0; i < NHEAD; i++) acc[i] = fmaf(v, al[i], acc[i]);
    }
    float* op = agg + (size_t)nod * (NHEAD * HID) + t;
    #pragma unroll
    for (int i = 0; i < NHEAD; i++) op[i * HID] = acc[i];
}

// ---------------- wtilde / wcat precompute ----------------
// FIXED: wsrc[h,k] = sum_c W1[k, h*256+c] * a_src1[h,c]   (k = input channel of hin)
__global__ void make_wtilde(const float* __restrict__ W1,
                            const float* __restrict__ as1,
                            const float* __restrict__ ad1) {
    int idx = blockIdx.x * blockDim.x + threadIdx.x;   // 0..2047
    if (idx >= NHEAD * HID) return;
    int h = idx >> 8;
    int k = idx & 255;
    const float* wrow = W1 + (size_t)k * (NHEAD * HID) + h * HID;
    const float* ar = as1 + h * HID;
    const float* dr = ad1 + h * HID;
    float s = 0.f, d = 0.f;
    for (int c = 0; c < HID; c++) {
        float w = wrow[c];
        s = fmaf(w, ar[c], s);
        d = fmaf(w, dr[c], d);
    }
    d_wsrc[idx] = s;
    d_wdst[idx] = d;
}

// wcat[(h*256+k), c] = W1[k, h*256+c]
__global__ void make_wcat(const float* __restrict__ W1) {
    int i = blockIdx.x * blockDim.x + threadIdx.x;
    if (i >= NHEAD * HID * HID) return;
    int c = i & 255;
    int hk = i >> 8;
    int k = hk & 255;
    int h = hk >> 8;
    d_wcat[i] = W1[(size_t)k * (NHEAD * HID) + h * HID + c];
}

// ---------------- batch norm ----------------
__global__ void bn_partial(const float* __restrict__ x) {
    int c = threadIdx.x;
    int nb = gridDim.x;
    int rows = (NN + nb - 1) / nb;
    int r0 = blockIdx.x * rows;
    int r1 = min(NN, r0 + rows);
    float s = 0.f, s2 = 0.f;
    for (int r = r0; r < r1; r++) {
        float v = x[(size_t)r * HID + c];
        s += v; s2 += v * v;
    }
    atomicAdd(&d_bnsum[c], s);
    atomicAdd(&d_bnsum2[c], s2);
}

__global__ void bn_final() {
    int c = threadIdx.x;
    float m = d_bnsum[c] * (1.f / NN);
    float v = d_bnsum2[c] * (1.f / NN) - m * m;
    d_mu[c] = m;
    d_rinv[c] = rsqrtf(v + EPSI);
}

__global__ void bn_apply(const float* __restrict__ x,
                         const float* __restrict__ g,
                         const float* __restrict__ be,
                         const float* __restrict__ resid,
                         float* __restrict__ out) {
    int i = blockIdx.x * blockDim.x + threadIdx.x;
    if (i >= NN * HID) return;
    int c = i & (HID - 1);
    float v = g[c] * (x[i] - d_mu[c]) * d_rinv[c] + be[c];
    v = (v > 0.f) ? v : (expf(v) - 1.f);
    if (resid) v += resid[i];
    out[i] = v;
}

// ---------------- split-K 128x128x8 double-buffered GEMM with fma.rn.f32x2 ----------------
__global__ __launch_bounds__(256, 2) void gemm128s(const float* __restrict__ A,
                                                   const float* __restrict__ B,
                                                   float* __restrict__ Cpart,
                                                   int M, int Nc, int lda, int ksz) {
    __shared__ float As[2][8][132];   // [buf][k][m]
    __shared__ float Bs[2][8][132];   // [buf][k][n]

    const int tid  = threadIdx.x;
    const int row0 = blockIdx.y * 128;
    const int col0 = blockIdx.x * 128;
    const int k0   = blockIdx.z * ksz;

    const int arow = tid >> 1;
    const int akg  = (tid & 1) * 4;
    const int bkr  = tid >> 5;
    const int bc4  = (tid & 31) * 4;

    const int lane = tid & 31;
    const int warp = tid >> 5;
    const int m0 = (warp & 3) * 32 + (lane >> 3) * 4;
    const int n0 = (warp >> 2) * 64 + (lane & 7) * 4;

    const int gra = row0 + arow;
    const int gcb = col0 + bc4;

    ull acc[8][4];
    #pragma unroll
    for (int i = 0; i < 8; i++)
        #pragma unroll
        for (int j = 0; j < 4; j++) acc[i][j] = 0ull;

    float aL[4], bL[4];

    auto load_tile = [&](int kabs) {
        if (gra < M) {
            const float4 v = *(const float4*)&A[(size_t)gra * lda + kabs + akg];
            aL[0] = v.x; aL[1] = v.y; aL[2] = v.z; aL[3] = v.w;
        } else {
            aL[0] = aL[1] = aL[2] = aL[3] = 0.f;
        }
        const float* Brow = B + (size_t)(kabs + bkr) * Nc;
        if (gcb + 4 <= Nc) {
            const float4 v = *(const float4*)&Brow[gcb];
            bL[0] = v.x; bL[1] = v.y; bL[2] = v.z; bL[3] = v.w;
        } else {
            #pragma unroll
            for (int i = 0; i < 4; i++)
                bL[i] = (gcb + i < Nc) ? Brow[gcb + i] : 0.f;
        }
    };
    auto store_tile = [&](int buf) {
        #pragma unroll
        for (int i = 0; i < 4; i++) As[buf][akg + i][arow] = aL[i];
        *(float4*)&Bs[buf][bkr][bc4] = make_float4(bL[0], bL[1], bL[2], bL[3]);
    };

    load_tile(k0);
    store_tile(0);
    __syncthreads();

    const int ntiles = ksz >> 3;
    for (int t = 0; t < ntiles; t++) {
        const int buf = t & 1;
        if (t + 1 < ntiles) load_tile(k0 + ((t + 1) << 3));
        #pragma unroll
        for (int k = 0; k < 8; k++) {
            float a_f[8];
            *(float4*)&a_f[0] = *(const float4*)&As[buf][k][m0];
            *(float4*)&a_f[4] = *(const float4*)&As[buf][k][m0 + 16];
            float4 bv0 = *(const float4*)&Bs[buf][k][n0];
            float4 bv1 = *(const float4*)&Bs[buf][k][n0 + 32];
            ull b2[4];
            asm("mov.b64 %0, {%1, %2};" : "=l"(b2[0]) : "f"(bv0.x), "f"(bv0.y));
            asm("mov.b64 %0, {%1, %2};" : "=l"(b2[1]) : "f"(bv0.z), "f"(bv0.w));
            asm("mov.b64 %0, {%1, %2};" : "=l"(b2[2]) : "f"(bv1.x), "f"(bv1.y));
            asm("mov.b64 %0, {%1, %2};" : "=l"(b2[3]) : "f"(bv1.z), "f"(bv1.w));
            #pragma unroll
            for (int i = 0; i < 8; i++) {
                ull a2;
                asm("mov.b64 %0, {%1, %1};" : "=l"(a2) : "f"(a_f[i]));
                #pragma unroll
                for (int j = 0; j < 4; j++)
                    asm("fma.rn.f32x2 %0, %1, %2, %0;"
                        : "+l"(acc[i][j]) : "l"(a2), "l"(b2[j]));
            }
        }
        if (t + 1 < ntiles) {
            store_tile(buf ^ 1);
            __syncthreads();
        }
    }

    float* Cp = Cpart + (size_t)blockIdx.z * M * Nc;
    #pragma unroll
    for (int i = 0; i < 8; i++) {
        const int gm = row0 + ((i < 4) ? (m0 + i) : (m0 + 16 + i - 4));
        if (gm >= M) continue;
        float* Crow = Cp + (size_t)gm * Nc;
        #pragma unroll
        for (int jj = 0; jj < 2; jj++) {
            const int gn = col0 + n0 + jj * 32;
            float v[4];
            asm("mov.b64 {%0, %1}, %2;" : "=f"(v[0]), "=f"(v[1]) : "l"(acc[i][jj * 2]));
            asm("mov.b64 {%0, %1}, %2;" : "=f"(v[2]), "=f"(v[3]) : "l"(acc[i][jj * 2 + 1]));
            if (gn + 4 <= Nc) {
                *(float4*)&Crow[gn] = make_float4(v[0], v[1], v[2], v[3]);
            } else {
                #pragma unroll
                for (int j = 0; j < 4; j++)
                    if (gn + j < Nc) Crow[gn + j] = v[j];
            }
        }
    }
}

// sum the 4 split-K partials, scale, add bias
__global__ void reduce4(const float* __restrict__ part, float* __restrict__ out,
                        const float* __restrict__ bias, float scale, int M, int Nc) {
    int i = blockIdx.x * blockDim.x + threadIdx.x;
    if (i >= M * Nc) return;
    size_t st = (size_t)M * Nc;
    float v = part[i] + part[i + st] + part[i + 2 * st] + part[i + 3 * st];
    v *= scale;
    if (bias) v += bias[i % Nc];
    out[i] = v;
}

// ---------------- host launcher ----------------
extern "C" void kernel_launch(void* const* d_in, const int* in_sizes, int n_in,
                              void* d_out, int out_size) {
    (void)in_sizes; (void)n_in; (void)out_size;
    const float* x   = (const float*)d_in[0];
    const int*   ei  = (const int*)d_in[1];
    const float* W0  = (const float*)d_in[2];
    const float* as0 = (const float*)d_in[3];
    const float* ad0 = (const float*)d_in[4];
    const float* b0  = (const float*)d_in[5];
    const float* g0  = (const float*)d_in[6];
    const float* be0 = (const float*)d_in[7];
    const float* W1  = (const float*)d_in[8];
    const float* as1 = (const float*)d_in[9];
    const float* ad1 = (const float*)d_in[10];
    const float* b1  = (const float*)d_in[11];
    const float* g1  = (const float*)d_in[12];
    const float* be1 = (const float*)d_in[13];
    const float* Wc  = (const float*)d_in[14];
    const float* bc  = (const float*)d_in[15];
    float* out = (float*)d_out;
    const int* srcp = ei;
    const int* dstp = ei + EIN;

    void *p_counts, *p_cursor, *p_bnsum, *p_bnsum2;
    void *p_h0, *p_hin, *p_agg, *p_part, *p_h2, *p_out0, *p_out1, *p_wcat;
    cudaGetSymbolAddress(&p_counts, d_counts);
    cudaGetSymbolAddress(&p_cursor, d_cursor);
    cudaGetSymbolAddress(&p_bnsum,  d_bnsum);
    cudaGetSymbolAddress(&p_bnsum2, d_bnsum2);
    cudaGetSymbolAddress(&p_h0,   d_h0);
    cudaGetSymbolAddress(&p_hin,  d_hin);
    cudaGetSymbolAddress(&p_agg,  d_agg);
    cudaGetSymbolAddress(&p_part, d_part);
    cudaGetSymbolAddress(&p_h2,   d_h2);
    cudaGetSymbolAddress(&p_out0, d_out0);
    cudaGetSymbolAddress(&p_out1, d_out1);
    cudaGetSymbolAddress(&p_wcat, d_wcat);
    float* h0   = (float*)p_h0;
    float* hin  = (float*)p_hin;
    float* agg  = (float*)p_agg;
    float* part = (float*)p_part;
    float* h2   = (float*)p_h2;
    float* out0 = (float*)p_out0;
    float* out1 = (float*)p_out1;
    float* wcat = (float*)p_wcat;

    // ---- CSR build (shared by both layers) + W1 repacks (independent) ----
    cudaMemsetAsync(p_counts, 0, (NN + 1) * sizeof(int));
    cudaMemsetAsync(p_cursor, 0, NN * sizeof(int));
    count_kernel<<<(ETOT + 255) / 256, 256>>>(dstp);
    scan_kernel<<<1, 1024>>>();
    place_kernel<<<(ETOT + 255) / 256, 256>>>(srcp, dstp);
    make_wtilde<<<(NHEAD * HID + 255) / 256, 256>>>(W1, as1, ad1);
    make_wcat<<<(NHEAD * HID * HID + 255) / 256, 256>>>(W1);

    // ---- layer 0 ----
    gemm128s<<<dim3(HID / 128, (NN + 127) / 128, 4), 256>>>(x, W0, part, NN, HID, HID, HID / 4);
    reduce4<<<(NN * HID + 255) / 256, 256>>>(part, h0, nullptr, 1.f, NN, HID);
    attn_scores<<<(NN * NHEAD) / 8, 256>>>(h0, as0, ad0, HID / NHEAD);
    edge_softmax<<<(NN + 3) / 4, 128>>>();
    aggregate_c32<<<NN, HID>>>(h0, b0, out0);
    cudaMemsetAsync(p_bnsum, 0, HID * sizeof(float));
    cudaMemsetAsync(p_bnsum2, 0, HID * sizeof(float));
    bn_partial<<<128, HID>>>(out0);
    bn_final<<<1, HID>>>();
    bn_apply<<<(NN * HID + 255) / 256, 256>>>(out0, g0, be0, nullptr, hin);

    // ---- layer 1 (h1 never materialized) ----
    attn_scores_lin<<<(NN * 32 + 255) / 256, 256>>>(hin);
    edge_softmax<<<(NN + 3) / 4, 128>>>();
    aggregate8<<<NN, HID>>>(hin, agg);
    gemm128s<<<dim3(HID / 128, (NN + 127) / 128, 4), 256>>>(agg, wcat, part, NN, HID,
                                                            NHEAD * HID, NHEAD * HID / 4);
    reduce4<<<(NN * HID + 255) / 256, 256>>>(part, out1, b1, 1.f / NHEAD, NN, HID);
    cudaMemsetAsync(p_bnsum, 0, HID * sizeof(float));
    cudaMemsetAsync(p_bnsum2, 0, HID * sizeof(float));
    bn_partial<<<128, HID>>>(out1);
    bn_final<<<1, HID>>>();
    bn_apply<<<(NN * HID + 255) / 256, 256>>>(out1, g1, be1, hin, h2);

    // ---- classifier ----
    gemm128s<<<dim3(1, (NN + 127) / 128, 4), 256>>>(h2, Wc, part, NN, 40, HID, HID / 4);
    reduce4<<<(NN * 40 + 255) / 256, 256>>>(part, out, bc, 1.f, NN, 40);
}

// round 5
// speedup vs baseline: 1.4504x; 1.4504x over previous
#include <cuda_runtime.h>
#include <math.h>

#define NN    10000
#define EIN   160000
#define ETOT  170000
#define NHEAD 8
#define HID   256
#define EPSI  1e-5f
#define SLOPE 0.2f

// ---------------- scratch (device globals; no allocation allowed) ----------------
__device__ float d_h0[NN * HID];            // x @ W0 (layer0 features)
__device__ float d_hin[NN * HID];           // elu(bn(layer0))
__device__ float d_agg[NN * HID * NHEAD];   // per-head aggregated hin  [N,H,256]
__device__ float d_part[4 * NN * HID];      // split-K partials
__device__ float d_out0[NN * HID];
__device__ float d_out1[NN * HID];
__device__ float d_h2[NN * HID];
__device__ float d_ss[NN * NHEAD];
__device__ float d_sd[NN * NHEAD];
__device__ float d_wsrc[NHEAD * HID];       // folded a_src1 through W1
__device__ float d_wdst[NHEAD * HID];
__device__ int   d_counts[NN + 1];
__device__ int   d_offsets[NN + 1];
__device__ int   d_cursor[NN];
__device__ int   d_srcs[ETOT];
__device__ float d_alpha[ETOT * NHEAD];
__device__ float d_bnsum[HID];
__device__ float d_bnsum2[HID];
__device__ float d_mu[HID];
__device__ float d_rinv[HID];

// ---------------- CSR build ----------------
__global__ void count_kernel(const int* __restrict__ dst) {
    int i = blockIdx.x * blockDim.x + threadIdx.x;
    if (i >= ETOT) return;
    int d = (i < EIN) ? dst[i] : (i - EIN);
    atomicAdd(&d_counts[d], 1);
}

__global__ void scan_kernel() {
    __shared__ int sums[1024];
    const int n = NN;
    const int chunk = (n + 1023) / 1024;
    int tid = threadIdx.x;
    int start = tid * chunk;
    int local = 0;
    for (int i = 0; i < chunk; i++)
        if (start + i < n) local += d_counts[start + i];
    sums[tid] = local;
    __syncthreads();
    for (int off = 1; off < 1024; off <<= 1) {
        int v = (tid >= off) ? sums[tid - off] : 0;
        __syncthreads();
        sums[tid] += v;
        __syncthreads();
    }
    int run = (tid == 0) ? 0 : sums[tid - 1];
    for (int i = 0; i < chunk; i++) {
        if (start + i < n) {
            d_offsets[start + i] = run;
            run += d_counts[start + i];
        }
    }
    if (tid == 1023) d_offsets[n] = sums[1023];
}

__global__ void place_kernel(const int* __restrict__ src, const int* __restrict__ dst) {
    int i = blockIdx.x * blockDim.x + threadIdx.x;
    if (i >= ETOT) return;
    int s, d;
    if (i < EIN) { s = src[i]; d = dst[i]; }
    else         { s = d = i - EIN; }
    int pos = d_offsets[d] + atomicAdd(&d_cursor[d], 1);
    d_srcs[pos] = s;
}

// ---------------- attention scores (layer0: per-head feature dot) ----------------
__global__ void attn_scores(const float* __restrict__ h,
                            const float* __restrict__ a_src,
                            const float* __restrict__ a_dst, int C) {
    int w = (blockIdx.x * blockDim.x + threadIdx.x) >> 5;
    if (w >= NN * NHEAD) return;
    int node = w / NHEAD, head = w % NHEAD;
    int lane = threadIdx.x & 31;
    const float* hp = h + (size_t)node * NHEAD * C + head * C;
    const float* asrc = a_src + head * C;
    const float* adst = a_dst + head * C;
    float ss = 0.f, sd = 0.f;
    for (int c = lane; c < C; c += 32) {
        float hv = hp[c];
        ss += hv * asrc[c];
        sd += hv * adst[c];
    }
    #pragma unroll
    for (int o = 16; o > 0; o >>= 1) {
        ss += __shfl_xor_sync(0xffffffffu, ss, o);
        sd += __shfl_xor_sync(0xffffffffu, sd, o);
    }
    if (lane == 0) {
        d_ss[node * NHEAD + head] = ss;
        d_sd[node * NHEAD + head] = sd;
    }
}

// ---------------- layer1 scores: s[n,h] = dot(hin[n,:], wtilde[h,:]) ----------------
__global__ void attn_scores_lin(const float* __restrict__ hin) {
    int w = (blockIdx.x * blockDim.x + threadIdx.x) >> 5;
    if (w >= NN) return;
    int lane = threadIdx.x & 31;
    const float* hp = hin + (size_t)w * HID;
    float as[NHEAD], ad[NHEAD];
    #pragma unroll
    for (int h = 0; h < NHEAD; h++) { as[h] = 0.f; ad[h] = 0.f; }
    for (int c = lane; c < HID; c += 32) {
        float v = hp[c];
        #pragma unroll
        for (int h = 0; h < NHEAD; h++) {
            as[h] = fmaf(v, d_wsrc[h * HID + c], as[h]);
            ad[h] = fmaf(v, d_wdst[h * HID + c], ad[h]);
        }
    }
    #pragma unroll
    for (int h = 0; h < NHEAD; h++) {
        #pragma unroll
        for (int o = 16; o > 0; o >>= 1) {
            as[h] += __shfl_xor_sync(0xffffffffu, as[h], o);
            ad[h] += __shfl_xor_sync(0xffffffffu, ad[h], o);
        }
    }
    if (lane == 0) {
        #pragma unroll
        for (int h = 0; h < NHEAD; h++) {
            d_ss[w * NHEAD + h] = as[h];
            d_sd[w * NHEAD + h] = ad[h];
        }
    }
}

// ---------------- per-dst edge softmax ----------------
__global__ void edge_softmax() {
    int w = (blockIdx.x * blockDim.x + threadIdx.x) >> 5;
    if (w >= NN) return;
    int lane = threadIdx.x & 31;
    int beg = d_offsets[w], end = d_offsets[w + 1];
    float sd[NHEAD];
    #pragma unroll
    for (int h = 0; h < NHEAD; h++) sd[h] = d_sd[w * NHEAD + h];

    float mx[NHEAD];
    #pragma unroll
    for (int h = 0; h < NHEAD; h++) mx[h] = -1e30f;
    for (int p = beg + lane; p < end; p += 32) {
        int s = d_srcs[p];
        #pragma unroll
        for (int h = 0; h < NHEAD; h++) {
            float sc = d_ss[s * NHEAD + h] + sd[h];
            sc = (sc >= 0.f) ? sc : SLOPE * sc;
            mx[h] = fmaxf(mx[h], sc);
        }
    }
    #pragma unroll
    for (int h = 0; h < NHEAD; h++)
        #pragma unroll
        for (int o = 16; o > 0; o >>= 1)
            mx[h] = fmaxf(mx[h], __shfl_xor_sync(0xffffffffu, mx[h], o));

    float sum[NHEAD];
    #pragma unroll
    for (int h = 0; h < NHEAD; h++) sum[h] = 0.f;
    for (int p = beg + lane; p < end; p += 32) {
        int s = d_srcs[p];
        #pragma unroll
        for (int h = 0; h < NHEAD; h++) {
            float sc = d_ss[s * NHEAD + h] + sd[h];
            sc = (sc >= 0.f) ? sc : SLOPE * sc;
            sum[h] += __expf(sc - mx[h]);
        }
    }
    #pragma unroll
    for (int h = 0; h < NHEAD; h++)
        #pragma unroll
        for (int o = 16; o > 0; o >>= 1)
            sum[h] += __shfl_xor_sync(0xffffffffu, sum[h], o);

    float rinv[NHEAD];
    #pragma unroll
    for (int h = 0; h < NHEAD; h++) rinv[h] = 1.f / sum[h];

    for (int p = beg + lane; p < end; p += 32) {
        int s = d_srcs[p];
        #pragma unroll
        for (int h = 0; h < NHEAD; h++) {
            float sc = d_ss[s * NHEAD + h] + sd[h];
            sc = (sc >= 0.f) ? sc : SLOPE * sc;
            d_alpha[p * NHEAD + h] = __expf(sc - mx[h]) * rinv[h];
        }
    }
}

// ---------------- aggregation ----------------
// layer0: C=32 concat; thread t = channel, head = t>>5
__global__ void aggregate_c32(const float* __restrict__ h,
                              const float* __restrict__ bias,
                              float* __restrict__ out) {
    int nod = blockIdx.x;
    int t = threadIdx.x;
    int head = t >> 5;
    int beg = d_offsets[nod], end = d_offsets[nod + 1];
    float acc = 0.f;
    for (int p = beg; p < end; p++) {
        float a = d_alpha[p * NHEAD + head];
        acc = fmaf(h[(size_t)d_srcs[p] * HID + t], a, acc);
    }
    out[(size_t)nod * HID + t] = acc + bias[t];
}

// layer1 pre-GEMM aggregation: agg[n,h,k] = sum_p alpha[p,h] * hin[src_p, k]
__global__ void aggregate8(const float* __restrict__ hin, float* __restrict__ agg) {
    int nod = blockIdx.x;
    int t = threadIdx.x;
    int beg = d_offsets[nod], end = d_offsets[nod + 1];
    float acc[NHEAD];
    #pragma unroll
    for (int i = 0; i < NHEAD; i++) acc[i] = 0.f;
    for (int p = beg; p < end; p++) {
        int s = d_srcs[p];
        float v = hin[(size_t)s * HID + t];
        float al[NHEAD];
        #pragma unroll
        for (int i = 0; i < NHEAD; i++) al[i] = d_alpha[p * NHEAD + i];
        #pragma unroll
        for (int i = 0; i < NHEAD; i++) acc[i] = fmaf(v, al[i], acc[i]);
    }
    float* op = agg + (size_t)nod * (NHEAD * HID) + t;
    #pragma unroll
    for (int i = 0; i < NHEAD; i++) op[i * HID] = acc[i];
}

// ---------------- wtilde precompute (warp per output) ----------------
// wsrc[h,k] = sum_c W1[k, h*256+c] * a_src1[h,c]
__global__ void make_wtilde(const float* __restrict__ W1,
                            const float* __restrict__ as1,
                            const float* __restrict__ ad1) {
    int w = (blockIdx.x * blockDim.x + threadIdx.x) >> 5;
    if (w >= NHEAD * HID) return;
    int lane = threadIdx.x & 31;
    int h = w >> 8;
    int k = w & 255;
    const float* wrow = W1 + (size_t)k * (NHEAD * HID) + h * HID;
    const float* ar = as1 + h * HID;
    const float* dr = ad1 + h * HID;
    float s = 0.f, d = 0.f;
    for (int c = lane; c < HID; c += 32) {
        float wv = wrow[c];
        s = fmaf(wv, ar[c], s);
        d = fmaf(wv, dr[c], d);
    }
    #pragma unroll
    for (int o = 16; o > 0; o >>= 1) {
        s += __shfl_xor_sync(0xffffffffu, s, o);
        d += __shfl_xor_sync(0xffffffffu, d, o);
    }
    if (lane == 0) {
        d_wsrc[w] = s;
        d_wdst[w] = d;
    }
}

// ---------------- batch norm ----------------
__global__ void bn_partial(const float* __restrict__ x) {
    int c = threadIdx.x;
    int nb = gridDim.x;
    int rows = (NN + nb - 1) / nb;
    int r0 = blockIdx.x * rows;
    int r1 = min(NN, r0 + rows);
    float s = 0.f, s2 = 0.f;
    for (int r = r0; r < r1; r++) {
        float v = x[(size_t)r * HID + c];
        s += v; s2 += v * v;
    }
    atomicAdd(&d_bnsum[c], s);
    atomicAdd(&d_bnsum2[c], s2);
}

__global__ void bn_final() {
    int c = threadIdx.x;
    float m = d_bnsum[c] * (1.f / NN);
    float v = d_bnsum2[c] * (1.f / NN) - m * m;
    d_mu[c] = m;
    d_rinv[c] = rsqrtf(v + EPSI);
}

__global__ void bn_apply(const float* __restrict__ x,
                         const float* __restrict__ g,
                         const float* __restrict__ be,
                         const float* __restrict__ resid,
                         float* __restrict__ out) {
    int i = blockIdx.x * blockDim.x + threadIdx.x;
    if (i >= NN * HID) return;
    int c = i & (HID - 1);
    float v = g[c] * (x[i] - d_mu[c]) * d_rinv[c] + be[c];
    v = (v > 0.f) ? v : (expf(v) - 1.f);
    if (resid) v += resid[i];
    out[i] = v;
}

// ---------------- tf32 tensor-core GEMM (mma.sync m16n8k8), split-K ----------------
// Cpart[z] = A[:, k0:k0+ksz] @ B[k0:k0+ksz, :]
// bperm: B row r read from W1[(r&255)*2048 + (r>>8)*256 + c]  (layer-1 permuted W1)
__device__ __forceinline__ unsigned f2tf32(float f) {
    unsigned u;
    asm("cvt.rna.tf32.f32 %0, %1;" : "=r"(u) : "f"(f));
    return u;
}

__global__ __launch_bounds__(256, 2) void gemm_tf32(const float* __restrict__ A,
                                                    const float* __restrict__ B,
                                                    float* __restrict__ Cpart,
                                                    int M, int Nc, int lda, int ksz,
                                                    int bperm) {
    __shared__ float As[2][128][20];   // [buf][m][k16+pad] -> conflict-free frag loads
    __shared__ float Bs[2][16][136];   // [buf][k][n128+pad]

    const int tid  = threadIdx.x;
    const int row0 = blockIdx.y * 128;
    const int col0 = blockIdx.x * 128;
    const int k0   = blockIdx.z * ksz;

    // global loaders
    const int arow = tid >> 1;          // 0..127
    const int akg  = (tid & 1) * 8;     // 0 / 8
    const int bkr  = tid >> 4;          // 0..15
    const int bc8  = (tid & 15) * 8;    // 0..120

    const int lane = tid & 31;
    const int warp = tid >> 5;
    const int wm = (warp >> 2) * 64;    // 0 / 64
    const int wn = (warp & 3) * 32;     // 0,32,64,96
    const int g  = lane >> 2;           // 0..7
    const int t  = lane & 3;            // 0..3

    float c[4][4][4];
    #pragma unroll
    for (int mi = 0; mi < 4; mi++)
        #pragma unroll
        for (int ni = 0; ni < 4; ni++)
            #pragma unroll
            for (int q = 0; q < 4; q++) c[mi][ni][q] = 0.f;

    unsigned aL[8], bL[8];

    auto load_tile = [&](int kabs) {
        const int gra = row0 + arow;
        if (gra < M) {
            const float4 v0 = *(const float4*)&A[(size_t)gra * lda + kabs + akg];
            const float4 v1 = *(const float4*)&A[(size_t)gra * lda + kabs + akg + 4];
            aL[0] = f2tf32(v0.x); aL[1] = f2tf32(v0.y); aL[2] = f2tf32(v0.z); aL[3] = f2tf32(v0.w);
            aL[4] = f2tf32(v1.x); aL[5] = f2tf32(v1.y); aL[6] = f2tf32(v1.z); aL[7] = f2tf32(v1.w);
        } else {
            #pragma unroll
            for (int i = 0; i < 8; i++) aL[i] = 0u;
        }
        const int r = kabs + bkr;
        const float* Brow = bperm ? (B + (size_t)(r & 255) * (NHEAD * HID) + (r >> 8) * HID)
                                  : (B + (size_t)r * Nc);
        const int gc0 = col0 + bc8;
        if (gc0 + 8 <= Nc) {
            const float4 w0 = *(const float4*)&Brow[gc0];
            const float4 w1 = *(const float4*)&Brow[gc0 + 4];
            bL[0] = f2tf32(w0.x); bL[1] = f2tf32(w0.y); bL[2] = f2tf32(w0.z); bL[3] = f2tf32(w0.w);
            bL[4] = f2tf32(w1.x); bL[5] = f2tf32(w1.y); bL[6] = f2tf32(w1.z); bL[7] = f2tf32(w1.w);
        } else {
            #pragma unroll
            for (int i = 0; i < 8; i++)
                bL[i] = (gc0 + i < Nc) ? f2tf32(Brow[gc0 + i]) : 0u;
        }
    };
    auto store_tile = [&](int buf) {
        float4 s0, s1;
        s0.x = __uint_as_float(aL[0]); s0.y = __uint_as_float(aL[1]);
        s0.z = __uint_as_float(aL[2]); s0.w = __uint_as_float(aL[3]);
        s1.x = __uint_as_float(aL[4]); s1.y = __uint_as_float(aL[5]);
        s1.z = __uint_as_float(aL[6]); s1.w = __uint_as_float(aL[7]);
        *(float4*)&As[buf][arow][akg]     = s0;
        *(float4*)&As[buf][arow][akg + 4] = s1;
        s0.x = __uint_as_float(bL[0]); s0.y = __uint_as_float(bL[1]);
        s0.z = __uint_as_float(bL[2]); s0.w = __uint_as_float(bL[3]);
        s1.x = __uint_as_float(bL[4]); s1.y = __uint_as_float(bL[5]);
        s1.z = __uint_as_float(bL[6]); s1.w = __uint_as_float(bL[7]);
        *(float4*)&Bs[buf][bkr][bc8]     = s0;
        *(float4*)&Bs[buf][bkr][bc8 + 4] = s1;
    };

    load_tile(k0);
    store_tile(0);
    __syncthreads();

    const int ntiles = ksz >> 4;
    for (int tt = 0; tt < ntiles; tt++) {
        const int buf = tt & 1;
        if (tt + 1 < ntiles) load_tile(k0 + ((tt + 1) << 4));
        #pragma unroll
        for (int kc = 0; kc < 16; kc += 8) {
            unsigned af[4][4], bf[4][2];
            #pragma unroll
            for (int mi = 0; mi < 4; mi++) {
                const int mb = wm + mi * 16;
                af[mi][0] = __float_as_uint(As[buf][mb + g][kc + t]);
                af[mi][1] = __float_as_uint(As[buf][mb + g + 8][kc + t]);
                af[mi][2] = __float_as_uint(As[buf][mb + g][kc + t + 4]);
                af[mi][3] = __float_as_uint(As[buf][mb + g + 8][kc + t + 4]);
            }
            #pragma unroll
            for (int ni = 0; ni < 4; ni++) {
                const int nb = wn + ni * 8;
                bf[ni][0] = __float_as_uint(Bs[buf][kc + t][nb + g]);
                bf[ni][1] = __float_as_uint(Bs[buf][kc + t + 4][nb + g]);
            }
            #pragma unroll
            for (int mi = 0; mi < 4; mi++)
                #pragma unroll
                for (int ni = 0; ni < 4; ni++)
                    asm volatile(
                        "mma.sync.aligned.m16n8k8.row.col.f32.tf32.tf32.f32 "
                        "{%0,%1,%2,%3}, {%4,%5,%6,%7}, {%8,%9}, {%0,%1,%2,%3};\n"
                        : "+f"(c[mi][ni][0]), "+f"(c[mi][ni][1]),
                          "+f"(c[mi][ni][2]), "+f"(c[mi][ni][3])
                        : "r"(af[mi][0]), "r"(af[mi][1]), "r"(af[mi][2]), "r"(af[mi][3]),
                          "r"(bf[ni][0]), "r"(bf[ni][1]));
        }
        if (tt + 1 < ntiles) {
            store_tile(buf ^ 1);
            __syncthreads();
        }
    }

    float* Cp = Cpart + (size_t)blockIdx.z * M * Nc;
    #pragma unroll
    for (int mi = 0; mi < 4; mi++) {
        #pragma unroll
        for (int half = 0; half < 2; half++) {
            const int gm = row0 + wm + mi * 16 + g + half * 8;
            if (gm >= M) continue;
            float* Crow = Cp + (size_t)gm * Nc;
            #pragma unroll
            for (int ni = 0; ni < 4; ni++) {
                const int gn = col0 + wn + ni * 8 + 2 * t;
                if (gn + 2 <= Nc) {
                    float2 v;
                    v.x = c[mi][ni][half * 2];
                    v.y = c[mi][ni][half * 2 + 1];
                    *(float2*)&Crow[gn] = v;
                } else if (gn < Nc) {
                    Crow[gn] = c[mi][ni][half * 2];
                }
            }
        }
    }
}

// sum the 4 split-K partials, scale, add bias
__global__ void reduce4(const float* __restrict__ part, float* __restrict__ out,
                        const float* __restrict__ bias, float scale, int M, int Nc) {
    int i = blockIdx.x * blockDim.x + threadIdx.x;
    if (i >= M * Nc) return;
    size_t st = (size_t)M * Nc;
    float v = part[i] + part[i + st] + part[i + 2 * st] + part[i + 3 * st];
    v *= scale;
    if (bias) v += bias[i % Nc];
    out[i] = v;
}

// ---------------- host launcher ----------------
extern "C" void kernel_launch(void* const* d_in, const int* in_sizes, int n_in,
                              void* d_out, int out_size) {
    (void)in_sizes; (void)n_in; (void)out_size;
    const float* x   = (const float*)d_in[0];
    const int*   ei  = (const int*)d_in[1];
    const float* W0  = (const float*)d_in[2];
    const float* as0 = (const float*)d_in[3];
    const float* ad0 = (const float*)d_in[4];
    const float* b0  = (const float*)d_in[5];
    const float* g0  = (const float*)d_in[6];
    const float* be0 = (const float*)d_in[7];
    const float* W1  = (const float*)d_in[8];
    const float* as1 = (const float*)d_in[9];
    const float* ad1 = (const float*)d_in[10];
    const float* b1  = (const float*)d_in[11];
    const float* g1  = (const float*)d_in[12];
    const float* be1 = (const float*)d_in[13];
    const float* Wc  = (const float*)d_in[14];
    const float* bc  = (const float*)d_in[15];
    float* out = (float*)d_out;
    const int* srcp = ei;
    const int* dstp = ei + EIN;

    void *p_counts, *p_cursor, *p_bnsum, *p_bnsum2;
    void *p_h0, *p_hin, *p_agg, *p_part, *p_h2, *p_out0, *p_out1;
    cudaGetSymbolAddress(&p_counts, d_counts);
    cudaGetSymbolAddress(&p_cursor, d_cursor);
    cudaGetSymbolAddress(&p_bnsum,  d_bnsum);
    cudaGetSymbolAddress(&p_bnsum2, d_bnsum2);
    cudaGetSymbolAddress(&p_h0,   d_h0);
    cudaGetSymbolAddress(&p_hin,  d_hin);
    cudaGetSymbolAddress(&p_agg,  d_agg);
    cudaGetSymbolAddress(&p_part, d_part);
    cudaGetSymbolAddress(&p_h2,   d_h2);
    cudaGetSymbolAddress(&p_out0, d_out0);
    cudaGetSymbolAddress(&p_out1, d_out1);
    float* h0   = (float*)p_h0;
    float* hin  = (float*)p_hin;
    float* agg  = (float*)p_agg;
    float* part = (float*)p_part;
    float* h2   = (float*)p_h2;
    float* out0 = (float*)p_out0;
    float* out1 = (float*)p_out1;

    // ---- CSR build (the profiled 6th launch is the layer-0 tf32 GEMM) ----
    cudaMemsetAsync(p_counts, 0, (NN + 1) * sizeof(int));
    cudaMemsetAsync(p_cursor, 0, NN * sizeof(int));
    count_kernel<<<(ETOT + 255) / 256, 256>>>(dstp);
    scan_kernel<<<1, 1024>>>();
    place_kernel<<<(ETOT + 255) / 256, 256>>>(srcp, dstp);

    // ---- layer 0 ----
    gemm_tf32<<<dim3(HID / 128, (NN + 127) / 128, 4), 256>>>(x, W0, part, NN, HID, HID,
                                                             HID / 4, 0);
    reduce4<<<(NN * HID + 255) / 256, 256>>>(part, h0, nullptr, 1.f, NN, HID);
    make_wtilde<<<(NHEAD * HID * 32 + 255) / 256, 256>>>(W1, as1, ad1);
    attn_scores<<<(NN * NHEAD) / 8, 256>>>(h0, as0, ad0, HID / NHEAD);
    edge_softmax<<<(NN + 3) / 4, 128>>>();
    aggregate_c32<<<NN, HID>>>(h0, b0, out0);
    cudaMemsetAsync(p_bnsum, 0, HID * sizeof(float));
    cudaMemsetAsync(p_bnsum2, 0, HID * sizeof(float));
    bn_partial<<<128, HID>>>(out0);
    bn_final<<<1, HID>>>();
    bn_apply<<<(NN * HID + 255) / 256, 256>>>(out0, g0, be0, nullptr, hin);

    // ---- layer 1 (h1 never materialized; W1 permutation folded into GEMM) ----
    attn_scores_lin<<<(NN * 32 + 255) / 256, 256>>>(hin);
    edge_softmax<<<(NN + 3) / 4, 128>>>();
    aggregate8<<<NN, HID>>>(hin, agg);
    gemm_tf32<<<dim3(HID / 128, (NN + 127) / 128, 4), 256>>>(agg, W1, part, NN, HID,
                                                             NHEAD * HID, NHEAD * HID / 4, 1);
    reduce4<<<(NN * HID + 255) / 256, 256>>>(part, out1, b1, 1.f / NHEAD, NN, HID);
    cudaMemsetAsync(p_bnsum, 0, HID * sizeof(float));
    cudaMemsetAsync(p_bnsum2, 0, HID * sizeof(float));
    bn_partial<<<128, HID>>>(out1);
    bn_final<<<1, HID>>>();
    bn_apply<<<(NN * HID + 255) / 256, 256>>>(out1, g1, be1, hin, h2);

    // ---- classifier ----
    gemm_tf32<<<dim3(1, (NN + 127) / 128, 4), 256>>>(h2, Wc, part, NN, 40, HID, HID / 4, 0);
    reduce4<<<(NN * 40 + 255) / 256, 256>>>(part, out, bc, 1.f, NN, 40);
}